// round 10
// baseline (speedup 1.0000x reference)
#include <cuda_runtime.h>
#include <cuda_bf16.h>
#include <cstdint>
#include <math.h>

// Problem dims
#define VV 16000
#define BB 32
#define TT 256
#define EE 512
#define GE 2048          // 4*E
#define MROWS 8192       // B*T
#define NPADV 16128      // 63*256, padded vocab for GEMM tiles

#define NBLK 128
#define NTHR 256

// ---------------- scratch (device globals; no allocation allowed) -------------
__device__ __align__(16) float g_G   [(size_t)MROWS * GE];     // x@Wx+b (reused per layer)
__device__ __align__(16) float g_Hping[2 * BB * EE];           // h ping-pong [B][E]
__device__ __align__(16) __nv_bfloat16 g_Ahi[(size_t)MROWS * EE];   // A operand hi
__device__ __align__(16) __nv_bfloat16 g_Alo[(size_t)MROWS * EE];   // A operand lo
__device__ __align__(16) __nv_bfloat16 g_WThi[(size_t)NPADV * EE];  // W^T hi [Npad][512]
__device__ __align__(16) __nv_bfloat16 g_WTlo[(size_t)NPADV * EE];  // W^T lo
__device__ float g_nll [MROWS];
__device__ unsigned g_bar_cnt;
__device__ unsigned g_bar_gen;

// ---------------- helpers ----------------
__device__ __forceinline__ float sigm(float x) { return 1.0f / (1.0f + expf(-x)); }

__device__ __forceinline__ unsigned ld_acq(const unsigned* p) {
    unsigned v;
    asm volatile("ld.acquire.gpu.u32 %0, [%1];" : "=r"(v) : "l"(p) : "memory");
    return v;
}

__device__ __forceinline__ void cp_async16(unsigned int dst, const void* src) {
    asm volatile("cp.async.cg.shared.global [%0], [%1], 16;" :: "r"(dst), "l"(src));
}
__device__ __forceinline__ void cp_commit() { asm volatile("cp.async.commit_group;"); }
template<int N> __device__ __forceinline__ void cp_wait() {
    asm volatile("cp.async.wait_group %0;" :: "n"(N));
}

__device__ __forceinline__ void grid_barrier(unsigned& mygen) {
    __syncthreads();
    if (threadIdx.x == 0) {
        unsigned a = atomicAdd(&g_bar_cnt, 1u);
        if (a == NBLK - 1) {
            g_bar_cnt = 0u;
            __threadfence();
            atomicAdd(&g_bar_gen, 1u);
        } else {
            while (ld_acq(&g_bar_gen) == mygen) { }
        }
        mygen++;
    }
    __syncthreads();
}

// ---------------- mma.sync helpers (compute_80 PTX — HMMA on sm_103) ----------
__device__ __forceinline__ void ldsm4(unsigned& r0, unsigned& r1, unsigned& r2,
                                      unsigned& r3, unsigned addr) {
    asm volatile("ldmatrix.sync.aligned.m8n8.x4.shared.b16 {%0,%1,%2,%3}, [%4];"
                 : "=r"(r0), "=r"(r1), "=r"(r2), "=r"(r3) : "r"(addr));
}
__device__ __forceinline__ void mma16816(float* d, const unsigned* a, const unsigned* b) {
    asm volatile(
        "mma.sync.aligned.m16n8k16.row.col.f32.bf16.bf16.f32 "
        "{%0,%1,%2,%3}, {%4,%5,%6,%7}, {%8,%9}, {%0,%1,%2,%3};"
        : "+f"(d[0]), "+f"(d[1]), "+f"(d[2]), "+f"(d[3])
        : "r"(a[0]), "r"(a[1]), "r"(a[2]), "r"(a[3]), "r"(b[0]), "r"(b[1]));
}

// ---------------- init: reset barrier state ----------------
__global__ void init_kernel() {
    if (threadIdx.x == 0) { g_bar_cnt = 0u; g_bar_gen = 0u; }
}

// ---------------- embedding gather -> split bf16 A operand ----------------
__global__ void embed_kernel(const int* __restrict__ inputs, const float* __restrict__ Emat) {
    int idx = blockIdx.x * blockDim.x + threadIdx.x;
    if (idx >= MROWS * (EE / 4)) return;
    int r  = idx >> 7;        // row (t*B+b); E/4 = 128
    int e4 = idx & 127;
    int t = r >> 5;
    int b = r & 31;
    int tok = inputs[b * TT + t];
    float4 v = reinterpret_cast<const float4*>(Emat)[(size_t)tok * 128 + e4];
    size_t base = (size_t)r * EE + e4 * 4;
    __nv_bfloat162 h01 = __floats2bfloat162_rn(v.x, v.y);
    __nv_bfloat162 h23 = __floats2bfloat162_rn(v.z, v.w);
    *reinterpret_cast<__nv_bfloat162*>(&g_Ahi[base])     = h01;
    *reinterpret_cast<__nv_bfloat162*>(&g_Ahi[base + 2]) = h23;
    __nv_bfloat162 l01 = __floats2bfloat162_rn(v.x - __bfloat162float(h01.x),
                                               v.y - __bfloat162float(h01.y));
    __nv_bfloat162 l23 = __floats2bfloat162_rn(v.z - __bfloat162float(h23.x),
                                               v.w - __bfloat162float(h23.y));
    *reinterpret_cast<__nv_bfloat162*>(&g_Alo[base])     = l01;
    *reinterpret_cast<__nv_bfloat162*>(&g_Alo[base + 2]) = l23;
}

// ---------------- weight transpose + bf16 split: W[512][N] -> WT[Npad][512] ---
__global__ void transpose_split_kernel(const float* __restrict__ W, int N, int Npad) {
    __shared__ float tile[32][33];
    int bx = blockIdx.x * 32;   // n base
    int by = blockIdx.y * 32;   // k base
    int tx = threadIdx.x;       // 0..31
    int ty = threadIdx.y;       // 0..7
    #pragma unroll
    for (int j = 0; j < 4; j++) {
        int k = by + ty + j * 8;
        int n = bx + tx;
        tile[ty + j * 8][tx] = (n < N) ? W[(size_t)k * N + n] : 0.0f;
    }
    __syncthreads();
    #pragma unroll
    for (int j = 0; j < 4; j++) {
        int n = bx + ty + j * 8;
        int k = by + tx;
        float v = tile[tx][ty + j * 8];
        __nv_bfloat16 h = __float2bfloat16(v);
        g_WThi[(size_t)n * EE + k] = h;
        g_WTlo[(size_t)n * EE + k] = __float2bfloat16(v - __bfloat162float(h));
    }
}

// ---------------- bf16 mma GEMM: C[M x N_real] = A*W^T + bias ----------------
// Split handled as K-extension: K_eff = 3*512; phase 0: Ahi*Bhi,
// phase 1: Alo*Bhi, phase 2: Ahi*Blo.
// Tile 128x256, BK=64, 256 threads (8 warps, 2m x 4n), warp tile 64x64.
// 3-stage cp.async pipeline, ONE __syncthreads per 64-k chunk.
// swap_mn: if nonzero, blockIdx.x indexes M (wave shares A in L2).
#define TCM 128
#define TCN 256
#define LDT 72                            // bf16 per smem row (144 B, conflict-free)
#define ROWB (LDT * 2)                    // 144
#define TILEA_BYTES (TCM * ROWB)          // 18432
#define TILEB_BYTES (TCN * ROWB)          // 36864
#define STAGE_BYTES (TILEA_BYTES + TILEB_BYTES)   // 55296
#define NSTAGE 3
#define GEMM_SMEM (NSTAGE * STAGE_BYTES)  // 165888

__global__ __launch_bounds__(256, 1)
void gemm_mma(const __nv_bfloat16* __restrict__ Ahi, const __nv_bfloat16* __restrict__ Alo,
              const float* __restrict__ bias, float* __restrict__ C, int N_real,
              int swap_mn)
{
    extern __shared__ __align__(16) char smem[];
    __shared__ float sbias[TCN];

    int tid = threadIdx.x;
    int wid = tid >> 5;
    int lane = tid & 31;
    int wm = wid & 1;           // 0..1
    int wn = wid >> 1;          // 0..3
    int n0 = (swap_mn ? blockIdx.y : blockIdx.x) * TCN;
    int m0 = (swap_mn ? blockIdx.x : blockIdx.y) * TCM;

    unsigned sbase = (unsigned)__cvta_generic_to_shared(smem);

    for (int i = tid; i < TCN; i += 256) {
        int n = n0 + i;
        sbias[i] = (n < N_real) ? bias[n] : 0.0f;
    }

    int g  = lane >> 3;
    int lr = lane & 7;
    unsigned aoff[4];
    #pragma unroll
    for (int mi = 0; mi < 4; mi++)
        aoff[mi] = (unsigned)((wm * 64 + mi * 16 + (g & 1) * 8 + lr) * ROWB
                              + (g >> 1) * 16);
    unsigned boff[4];
    #pragma unroll
    for (int ni2 = 0; ni2 < 4; ni2++)
        boff[ni2] = (unsigned)(TILEA_BYTES + (wn * 64 + ni2 * 16 + (g >> 1) * 8 + lr) * ROWB
                               + (g & 1) * 16);

    float acc[4][8][4];
    #pragma unroll
    for (int i = 0; i < 4; i++)
        #pragma unroll
        for (int j = 0; j < 8; j++)
            #pragma unroll
            for (int r = 0; r < 4; r++) acc[i][j][r] = 0.0f;

    const int NCH = 24;   // 3 phases * 8 chunks of 64

    auto load_chunk = [&](int c, int stage) {
        int phase = c >> 3;
        int k0 = (c & 7) * 64;
        const __nv_bfloat16* Asrc = (phase == 1) ? Alo : Ahi;
        const __nv_bfloat16* Bsrc = (phase == 2) ? g_WTlo : g_WThi;
        unsigned dstA = sbase + stage * STAGE_BYTES;
        unsigned dstB = dstA + TILEA_BYTES;
        #pragma unroll
        for (int q = 0; q < 12; q++) {
            int idx = tid + q * 256;          // 0..3071
            if (idx < 1024) {
                int row = idx >> 3, gg = idx & 7;
                cp_async16(dstA + row * ROWB + gg * 16,
                           Asrc + (size_t)(m0 + row) * EE + k0 + gg * 8);
            } else {
                int idx2 = idx - 1024;        // 0..2047
                int row = idx2 >> 3, gg = idx2 & 7;
                cp_async16(dstB + row * ROWB + gg * 16,
                           Bsrc + (size_t)(n0 + row) * EE + k0 + gg * 8);
            }
        }
        cp_commit();
    };

    // prologue: fill 2 stages
    load_chunk(0, 0);
    load_chunk(1, 1);

    int stage = 0;
    #pragma unroll 1
    for (int c = 0; c < NCH; c++) {
        if (c + 2 < NCH) cp_wait<1>(); else cp_wait<0>();
        __syncthreads();
        if (c + 2 < NCH)
            load_chunk(c + 2, (c + 2) % NSTAGE);

        unsigned sb = sbase + stage * STAGE_BYTES;
        #pragma unroll
        for (int ks = 0; ks < 4; ks++) {
            unsigned a[4][4], b[8][2];
            #pragma unroll
            for (int mi = 0; mi < 4; mi++)
                ldsm4(a[mi][0], a[mi][1], a[mi][2], a[mi][3],
                      sb + aoff[mi] + ks * 32);
            #pragma unroll
            for (int ni2 = 0; ni2 < 4; ni2++)
                ldsm4(b[2 * ni2][0], b[2 * ni2][1], b[2 * ni2 + 1][0], b[2 * ni2 + 1][1],
                      sb + boff[ni2] + ks * 32);
            #pragma unroll
            for (int mi = 0; mi < 4; mi++)
                #pragma unroll
                for (int ni = 0; ni < 8; ni++)
                    mma16816(acc[mi][ni], a[mi], b[ni]);
        }
        stage = (stage + 1 == NSTAGE) ? 0 : stage + 1;
    }

    // epilogue: scattered float2 stores with bias
    int rbase = m0 + wm * 64 + (lane >> 2);
    int cbase = n0 + wn * 64 + 2 * (lane & 3);
    #pragma unroll
    for (int mi = 0; mi < 4; mi++) {
        #pragma unroll
        for (int ni = 0; ni < 8; ni++) {
            int col = cbase + ni * 8;
            if (col >= N_real) continue;
            int cl = (wn * 64 + ni * 8 + 2 * (lane & 3));
            float bx = sbias[cl], by = sbias[cl + 1];
            int r0 = rbase + mi * 16;
            float2 v0 = make_float2(acc[mi][ni][0] + bx, acc[mi][ni][1] + by);
            float2 v1 = make_float2(acc[mi][ni][2] + bx, acc[mi][ni][3] + by);
            *reinterpret_cast<float2*>(&C[(size_t)r0 * N_real + col]) = v0;
            *reinterpret_cast<float2*>(&C[(size_t)(r0 + 8) * N_real + col]) = v1;
        }
    }
}

// ---------------- persistent LSTM layer ----------------
#define SM_WS 0
#define SM_SH (16 * 512)                 // 8192 floats
#define SM_GS (SM_SH + 32 * 512)         // 24576
#define SM_CS (SM_GS + 512)              // 25088
#define SM_FLOATS (SM_CS + 128)          // 25216 -> 100864 bytes

__global__ __launch_bounds__(NTHR, 1)
void lstm_layer_persistent(const float* __restrict__ Gx,   // [T*B][2048], rows t*32+b
                           const float* __restrict__ Wh,   // [512][2048]
                           int rA, int rB, unsigned gen_base)
{
    extern __shared__ float smemf[];
    float* ws = smemf + SM_WS;
    float* sh = smemf + SM_SH;
    float* gs = smemf + SM_GS;
    float* cs = smemf + SM_CS;

    int tid = threadIdx.x;
    int e0 = blockIdx.x * 4;
    int b  = tid & 31;
    int cg = tid >> 5;                 // 0..7
    int c0 = cg * 2, c1 = c0 + 1;
    int col0 = ((c0 >> 2) << 9) + e0 + (c0 & 3);
    int col1 = ((c1 >> 2) << 9) + e0 + (c1 & 3);
    int bx7 = b & 7;

    for (int i = tid; i < 16 * 512; i += NTHR) {
        int c = i & 15, k = i >> 4;
        ws[c * 512 + k] = Wh[(size_t)k * 2048 + ((c >> 2) << 9) + e0 + (c & 3)];
    }
    if (tid < 128) cs[tid] = 0.0f;

    unsigned mygen = gen_base;
    unsigned int sh_u32 = (unsigned int)__cvta_generic_to_shared(sh);
    const float4* ws4 = (const float4*)ws;
    const float4* hp  = (const float4*)sh + b * 128;
    const float4* wp0 = ws4 + c0 * 128;
    const float4* wp1 = ws4 + c1 * 128;
    __syncthreads();

    #pragma unroll 1
    for (int t = 0; t < TT; t++) {
        const float* hg_r = g_Hping + ((t & 1) ? (BB * EE) : 0);
        float*       hg_w = g_Hping + ((t & 1) ? 0 : (BB * EE));

        float gx0 = Gx[(size_t)(t * 32 + b) * 2048 + col0];
        float gx1 = Gx[(size_t)(t * 32 + b) * 2048 + col1];

        float acc0 = 0.0f, acc1 = 0.0f;

        if (t > 0) {
            #pragma unroll
            for (int ch = 0; ch < 4; ch++) {
                #pragma unroll
                for (int q = 0; q < 4; q++) {
                    int m  = tid + q * 256;            // 0..1023
                    int bb = m >> 5, kk = m & 31;
                    int src4 = bb * 128 + ch * 32 + kk;
                    int dst4 = bb * 128 + (((ch * 32 + kk)) ^ (bb & 7));
                    cp_async16(sh_u32 + (unsigned int)dst4 * 16u,
                               (const float4*)hg_r + src4);
                }
                cp_commit();
            }

            #define LSTM_CHUNK(CH)                                            \
            {                                                                  \
                _Pragma("unroll")                                              \
                for (int kk = 0; kk < 32; kk++) {                              \
                    float4 hv = hp[((CH) * 32 + kk) ^ bx7];                    \
                    float4 w0 = wp0[(CH) * 32 + kk];                           \
                    float4 w1 = wp1[(CH) * 32 + kk];                           \
                    acc0 += hv.x * w0.x + hv.y * w0.y + hv.z * w0.z + hv.w * w0.w; \
                    acc1 += hv.x * w1.x + hv.y * w1.y + hv.z * w1.z + hv.w * w1.w; \
                }                                                              \
            }

            cp_wait<3>(); __syncthreads(); LSTM_CHUNK(0)
            cp_wait<2>(); __syncthreads(); LSTM_CHUNK(1)
            cp_wait<1>(); __syncthreads(); LSTM_CHUNK(2)
            cp_wait<0>(); __syncthreads(); LSTM_CHUNK(3)
            #undef LSTM_CHUNK
        }

        gs[c0 * 32 + b] = acc0 + gx0;
        gs[c1 * 32 + b] = acc1 + gx1;
        __syncthreads();

        if (tid < 128) {
            int b2 = tid & 31, e2 = tid >> 5;
            float iv = gs[(0  + e2) * 32 + b2];
            float jv = gs[(4  + e2) * 32 + b2];
            float fv = gs[(8  + e2) * 32 + b2];
            float ov = gs[(12 + e2) * 32 + b2];
            float cold = cs[tid];
            float cn = sigm(fv + 1.0f) * cold + sigm(iv) * tanhf(jv);
            float hn = sigm(ov) * tanhf(cn);
            cs[tid] = cn;
            hg_w[b2 * 512 + e0 + e2] = hn;
            size_t row = (size_t)(t * rA + b2 * rB) * EE + e0 + e2;
            __nv_bfloat16 hh = __float2bfloat16(hn);
            g_Ahi[row] = hh;
            g_Alo[row] = __float2bfloat16(hn - __bfloat162float(hh));
            __threadfence();
        }
        grid_barrier(mygen);
    }
}

// ---------------- softmax NLL per row (single pass, online, fast exp) ---------
__global__ void softmax_nll_kernel(const float* __restrict__ logits,
                                   const int* __restrict__ labels)
{
    int row = blockIdx.x;
    const float4* lr = reinterpret_cast<const float4*>(logits + (size_t)row * VV);
    int tid = threadIdx.x;
    __shared__ float redm[256];
    __shared__ float reds[256];

    float m = -1e30f, s = 0.0f;
    for (int i = tid; i < VV / 4; i += 256) {
        float4 v = lr[i];
        float cm = fmaxf(fmaxf(v.x, v.y), fmaxf(v.z, v.w));
        if (cm > m) { s *= __expf(m - cm); m = cm; }
        s += __expf(v.x - m) + __expf(v.y - m) + __expf(v.z - m) + __expf(v.w - m);
    }
    redm[tid] = m; reds[tid] = s;
    __syncthreads();
    for (int st = 128; st > 0; st >>= 1) {
        if (tid < st) {
            float m2 = redm[tid + st], s2 = reds[tid + st];
            float m1 = redm[tid],      s1 = reds[tid];
            float mm = fmaxf(m1, m2);
            redm[tid] = mm;
            reds[tid] = s1 * __expf(m1 - mm) + s2 * __expf(m2 - mm);
        }
        __syncthreads();
    }
    if (tid == 0) {
        float lv = logits[(size_t)row * VV + labels[row]];
        g_nll[row] = redm[0] + logf(reds[0]) - lv;
    }
}

__global__ void perplexity_kernel(float* __restrict__ out, long long out_size) {
    __shared__ float red[256];
    int tid = threadIdx.x;
    float s = 0.f;
    for (int i = tid; i < MROWS; i += 256) s += g_nll[i];
    red[tid] = s; __syncthreads();
    for (int st = 128; st > 0; st >>= 1) {
        if (tid < st) red[tid] += red[tid + st];
        __syncthreads();
    }
    if (tid == 0 && out_size > (long long)MROWS * VV)
        out[out_size - 1] = expf(red[0] / (float)MROWS);
}

// ---------------- host launch ----------------
extern "C" void kernel_launch(void* const* d_in, const int* in_sizes, int n_in,
                              void* d_out, int out_size)
{
    const int*   inputs = (const int*)  d_in[0];
    const int*   labels = (const int*)  d_in[1];
    const float* Emat   = (const float*)d_in[2];
    const float* Wx0    = (const float*)d_in[3];
    const float* Wh0    = (const float*)d_in[4];
    const float* b0     = (const float*)d_in[5];
    const float* Wx1    = (const float*)d_in[6];
    const float* Wh1    = (const float*)d_in[7];
    const float* b1     = (const float*)d_in[8];
    const float* Wd     = (const float*)d_in[9];
    const float* bd     = (const float*)d_in[10];
    float* out = (float*)d_out;

    float *pG;
    __nv_bfloat16 *pAhi, *pAlo;
    cudaGetSymbolAddress((void**)&pG,   g_G);
    cudaGetSymbolAddress((void**)&pAhi, g_Ahi);
    cudaGetSymbolAddress((void**)&pAlo, g_Alo);

    const int lstm_smem = SM_FLOATS * 4;
    cudaFuncSetAttribute(lstm_layer_persistent,
                         cudaFuncAttributeMaxDynamicSharedMemorySize, lstm_smem);
    cudaFuncSetAttribute(gemm_mma,
                         cudaFuncAttributeMaxDynamicSharedMemorySize, GEMM_SMEM);

    dim3 tsblk(32, 8);

    // 0) reset barrier state
    init_kernel<<<1, 32>>>();

    // 1) embedding gather -> split bf16 A operand (rows t*32+b)
    embed_kernel<<<(MROWS * (EE / 4) + 255) / 256, 256>>>(inputs, Emat);

    // 2) Wx0^T split; X0 = xs @ Wx0 + b0 -> g_G
    transpose_split_kernel<<<dim3(GE / 32, 16), tsblk>>>(Wx0, GE, GE);
    gemm_mma<<<dim3(GE / TCN, MROWS / TCM), 256, GEMM_SMEM>>>(pAhi, pAlo, b0, pG, GE, 0);

    // 3) layer-0 persistent scan (writes A = H0, rows t*32+b)
    lstm_layer_persistent<<<NBLK, NTHR, lstm_smem>>>(pG, Wh0,
                                                     /*rA=*/32, /*rB=*/1,
                                                     /*gen_base=*/0u);

    // 4) Wx1^T split; X1 = H0 @ Wx1 + b1 -> g_G
    transpose_split_kernel<<<dim3(GE / 32, 16), tsblk>>>(Wx1, GE, GE);
    gemm_mma<<<dim3(GE / TCN, MROWS / TCM), 256, GEMM_SMEM>>>(pAhi, pAlo, b1, pG, GE, 0);

    // 5) layer-1 persistent scan (writes A = H1, rows b*256+t)
    lstm_layer_persistent<<<NBLK, NTHR, lstm_smem>>>(pG, Wh1,
                                                     /*rA=*/1, /*rB=*/TT,
                                                     /*gen_base=*/(unsigned)TT);

    // 6) Wd^T split (padded to 16128); logits = H1 @ Wd + bd -> d_out
    //    swap_mn=1: wave shares the small A operand in L2 instead of streaming B
    transpose_split_kernel<<<dim3(NPADV / 32, 16), tsblk>>>(Wd, VV, NPADV);
    gemm_mma<<<dim3(MROWS / TCM, NPADV / TCN), 256, GEMM_SMEM>>>(pAhi, pAlo, bd, out, VV, 1);

    // 7) per-row NLL (single pass)
    softmax_nll_kernel<<<MROWS, 256>>>(out, labels);

    // 8) perplexity scalar
    perplexity_kernel<<<1, 256>>>(out, (long long)out_size);
}

// round 11
// speedup vs baseline: 1.0156x; 1.0156x over previous
#include <cuda_runtime.h>
#include <cuda_bf16.h>
#include <cstdint>
#include <math.h>

// Problem dims
#define VV 16000
#define BB 32
#define TT 256
#define EE 512
#define GE 2048          // 4*E
#define MROWS 8192       // B*T
#define NPADV 16128      // 126*128, padded vocab for GEMM tiles

#define NBLK 128
#define NTHR 256

// ---------------- scratch (device globals; no allocation allowed) -------------
__device__ __align__(16) float g_G   [(size_t)MROWS * GE];     // x@Wx+b (reused per layer)
__device__ __align__(16) float g_Hping[2 * BB * EE];           // h ping-pong [B][E]
__device__ __align__(16) __nv_bfloat16 g_Ahi[(size_t)MROWS * EE];   // A operand hi
__device__ __align__(16) __nv_bfloat16 g_Alo[(size_t)MROWS * EE];   // A operand lo
__device__ __align__(16) __nv_bfloat16 g_WThi[(size_t)NPADV * EE];  // W^T hi [Npad][512]
__device__ __align__(16) __nv_bfloat16 g_WTlo[(size_t)NPADV * EE];  // W^T lo
__device__ float g_nll [MROWS];
__device__ unsigned g_bar_cnt;
__device__ unsigned g_bar_gen;

// ---------------- helpers ----------------
__device__ __forceinline__ float sigm(float x) { return 1.0f / (1.0f + expf(-x)); }

__device__ __forceinline__ unsigned ld_acq(const unsigned* p) {
    unsigned v;
    asm volatile("ld.acquire.gpu.u32 %0, [%1];" : "=r"(v) : "l"(p) : "memory");
    return v;
}

__device__ __forceinline__ void cp_async16(unsigned int dst, const void* src) {
    asm volatile("cp.async.cg.shared.global [%0], [%1], 16;" :: "r"(dst), "l"(src));
}
__device__ __forceinline__ void cp_commit() { asm volatile("cp.async.commit_group;"); }
template<int N> __device__ __forceinline__ void cp_wait() {
    asm volatile("cp.async.wait_group %0;" :: "n"(N));
}

__device__ __forceinline__ void grid_barrier(unsigned& mygen) {
    __syncthreads();
    if (threadIdx.x == 0) {
        unsigned a = atomicAdd(&g_bar_cnt, 1u);
        if (a == NBLK - 1) {
            g_bar_cnt = 0u;
            __threadfence();
            atomicAdd(&g_bar_gen, 1u);
        } else {
            while (ld_acq(&g_bar_gen) == mygen) { }
        }
        mygen++;
    }
    __syncthreads();
}

// ---------------- mma.sync helpers (compute_80 PTX — HMMA on sm_103) ----------
__device__ __forceinline__ void ldsm4(unsigned& r0, unsigned& r1, unsigned& r2,
                                      unsigned& r3, unsigned addr) {
    asm volatile("ldmatrix.sync.aligned.m8n8.x4.shared.b16 {%0,%1,%2,%3}, [%4];"
                 : "=r"(r0), "=r"(r1), "=r"(r2), "=r"(r3) : "r"(addr));
}
__device__ __forceinline__ void mma16816(float* d, const unsigned* a, const unsigned* b) {
    asm volatile(
        "mma.sync.aligned.m16n8k16.row.col.f32.bf16.bf16.f32 "
        "{%0,%1,%2,%3}, {%4,%5,%6,%7}, {%8,%9}, {%0,%1,%2,%3};"
        : "+f"(d[0]), "+f"(d[1]), "+f"(d[2]), "+f"(d[3])
        : "r"(a[0]), "r"(a[1]), "r"(a[2]), "r"(a[3]), "r"(b[0]), "r"(b[1]));
}

// ---------------- init: reset barrier state ----------------
__global__ void init_kernel() {
    if (threadIdx.x == 0) { g_bar_cnt = 0u; g_bar_gen = 0u; }
}

// ---------------- embedding gather -> split bf16 A operand ----------------
__global__ void embed_kernel(const int* __restrict__ inputs, const float* __restrict__ Emat) {
    int idx = blockIdx.x * blockDim.x + threadIdx.x;
    if (idx >= MROWS * (EE / 4)) return;
    int r  = idx >> 7;        // row (t*B+b); E/4 = 128
    int e4 = idx & 127;
    int t = r >> 5;
    int b = r & 31;
    int tok = inputs[b * TT + t];
    float4 v = reinterpret_cast<const float4*>(Emat)[(size_t)tok * 128 + e4];
    size_t base = (size_t)r * EE + e4 * 4;
    __nv_bfloat162 h01 = __floats2bfloat162_rn(v.x, v.y);
    __nv_bfloat162 h23 = __floats2bfloat162_rn(v.z, v.w);
    *reinterpret_cast<__nv_bfloat162*>(&g_Ahi[base])     = h01;
    *reinterpret_cast<__nv_bfloat162*>(&g_Ahi[base + 2]) = h23;
    __nv_bfloat162 l01 = __floats2bfloat162_rn(v.x - __bfloat162float(h01.x),
                                               v.y - __bfloat162float(h01.y));
    __nv_bfloat162 l23 = __floats2bfloat162_rn(v.z - __bfloat162float(h23.x),
                                               v.w - __bfloat162float(h23.y));
    *reinterpret_cast<__nv_bfloat162*>(&g_Alo[base])     = l01;
    *reinterpret_cast<__nv_bfloat162*>(&g_Alo[base + 2]) = l23;
}

// ---------------- weight transpose + bf16 split: W[512][N] -> WT[Npad][512] ---
__global__ void transpose_split_kernel(const float* __restrict__ W, int N, int Npad) {
    __shared__ float tile[32][33];
    int bx = blockIdx.x * 32;   // n base
    int by = blockIdx.y * 32;   // k base
    int tx = threadIdx.x;       // 0..31
    int ty = threadIdx.y;       // 0..7
    #pragma unroll
    for (int j = 0; j < 4; j++) {
        int k = by + ty + j * 8;
        int n = bx + tx;
        tile[ty + j * 8][tx] = (n < N) ? W[(size_t)k * N + n] : 0.0f;
    }
    __syncthreads();
    #pragma unroll
    for (int j = 0; j < 4; j++) {
        int n = bx + ty + j * 8;
        int k = by + tx;
        float v = tile[tx][ty + j * 8];
        __nv_bfloat16 h = __float2bfloat16(v);
        g_WThi[(size_t)n * EE + k] = h;
        g_WTlo[(size_t)n * EE + k] = __float2bfloat16(v - __bfloat162float(h));
    }
}

// ---------------- bf16 mma GEMM: C[M x N_real] = A*W^T + bias ----------------
// Split handled as K-extension: K_eff = 3*512; phase 0: Ahi*Bhi,
// phase 1: Alo*Bhi, phase 2: Ahi*Blo.
// Tile 128x128, BK=64, 128 threads (4 warps, 2m x 2n), warp tile 64x64.
// 3-stage cp.async pipeline, ONE __syncthreads per 64-k chunk. 2 CTAs/SM.
// swap_mn: if nonzero, blockIdx.x indexes M (wave shares A in L2).
#define TCM 128
#define TCN 128
#define LDT 72                            // bf16 per smem row (144 B, conflict-free)
#define ROWB (LDT * 2)                    // 144
#define TILEA_BYTES (TCM * ROWB)          // 18432
#define TILEB_BYTES (TCN * ROWB)          // 18432
#define STAGE_BYTES (TILEA_BYTES + TILEB_BYTES)   // 36864
#define NSTAGE 3
#define GEMM_SMEM (NSTAGE * STAGE_BYTES)  // 110592

__global__ __launch_bounds__(128, 2)
void gemm_mma(const __nv_bfloat16* __restrict__ Ahi, const __nv_bfloat16* __restrict__ Alo,
              const float* __restrict__ bias, float* __restrict__ C, int N_real,
              int swap_mn)
{
    extern __shared__ __align__(16) char smem[];
    __shared__ float sbias[TCN];

    int tid = threadIdx.x;
    int wid = tid >> 5;
    int lane = tid & 31;
    int wm = wid & 1;           // 0..1
    int wn = wid >> 1;          // 0..1
    int n0 = (swap_mn ? blockIdx.y : blockIdx.x) * TCN;
    int m0 = (swap_mn ? blockIdx.x : blockIdx.y) * TCM;

    unsigned sbase = (unsigned)__cvta_generic_to_shared(smem);

    for (int i = tid; i < TCN; i += 128) {
        int n = n0 + i;
        sbias[i] = (n < N_real) ? bias[n] : 0.0f;
    }

    int g  = lane >> 3;
    int lr = lane & 7;
    unsigned aoff[4];
    #pragma unroll
    for (int mi = 0; mi < 4; mi++)
        aoff[mi] = (unsigned)((wm * 64 + mi * 16 + (g & 1) * 8 + lr) * ROWB
                              + (g >> 1) * 16);
    unsigned boff[4];
    #pragma unroll
    for (int ni2 = 0; ni2 < 4; ni2++)
        boff[ni2] = (unsigned)(TILEA_BYTES + (wn * 64 + ni2 * 16 + (g >> 1) * 8 + lr) * ROWB
                               + (g & 1) * 16);

    float acc[4][8][4];
    #pragma unroll
    for (int i = 0; i < 4; i++)
        #pragma unroll
        for (int j = 0; j < 8; j++)
            #pragma unroll
            for (int r = 0; r < 4; r++) acc[i][j][r] = 0.0f;

    const int NCH = 24;   // 3 phases * 8 chunks of 64

    auto load_chunk = [&](int c, int stage) {
        int phase = c >> 3;
        int k0 = (c & 7) * 64;
        const __nv_bfloat16* Asrc = (phase == 1) ? Alo : Ahi;
        const __nv_bfloat16* Bsrc = (phase == 2) ? g_WTlo : g_WThi;
        unsigned dstA = sbase + stage * STAGE_BYTES;
        unsigned dstB = dstA + TILEA_BYTES;
        #pragma unroll
        for (int q = 0; q < 16; q++) {
            int idx = tid + q * 128;          // 0..2047
            if (idx < 1024) {
                int row = idx >> 3, gg = idx & 7;
                cp_async16(dstA + row * ROWB + gg * 16,
                           Asrc + (size_t)(m0 + row) * EE + k0 + gg * 8);
            } else {
                int idx2 = idx - 1024;        // 0..1023
                int row = idx2 >> 3, gg = idx2 & 7;
                cp_async16(dstB + row * ROWB + gg * 16,
                           Bsrc + (size_t)(n0 + row) * EE + k0 + gg * 8);
            }
        }
        cp_commit();
    };

    // prologue: fill 2 stages
    load_chunk(0, 0);
    load_chunk(1, 1);

    int stage = 0;
    #pragma unroll 1
    for (int c = 0; c < NCH; c++) {
        if (c + 2 < NCH) cp_wait<1>(); else cp_wait<0>();
        __syncthreads();
        if (c + 2 < NCH)
            load_chunk(c + 2, (c + 2) % NSTAGE);

        unsigned sb = sbase + stage * STAGE_BYTES;
        #pragma unroll
        for (int ks = 0; ks < 4; ks++) {
            unsigned a[4][4], b[8][2];
            #pragma unroll
            for (int mi = 0; mi < 4; mi++)
                ldsm4(a[mi][0], a[mi][1], a[mi][2], a[mi][3],
                      sb + aoff[mi] + ks * 32);
            #pragma unroll
            for (int ni2 = 0; ni2 < 4; ni2++)
                ldsm4(b[2 * ni2][0], b[2 * ni2][1], b[2 * ni2 + 1][0], b[2 * ni2 + 1][1],
                      sb + boff[ni2] + ks * 32);
            #pragma unroll
            for (int mi = 0; mi < 4; mi++)
                #pragma unroll
                for (int ni = 0; ni < 8; ni++)
                    mma16816(acc[mi][ni], a[mi], b[ni]);
        }
        stage = (stage + 1 == NSTAGE) ? 0 : stage + 1;
    }

    // epilogue: scattered float2 stores with bias
    int rbase = m0 + wm * 64 + (lane >> 2);
    int cbase = n0 + wn * 64 + 2 * (lane & 3);
    #pragma unroll
    for (int mi = 0; mi < 4; mi++) {
        #pragma unroll
        for (int ni = 0; ni < 8; ni++) {
            int col = cbase + ni * 8;
            if (col >= N_real) continue;
            int cl = (wn * 64 + ni * 8 + 2 * (lane & 3));
            float bx = sbias[cl], by = sbias[cl + 1];
            int r0 = rbase + mi * 16;
            float2 v0 = make_float2(acc[mi][ni][0] + bx, acc[mi][ni][1] + by);
            float2 v1 = make_float2(acc[mi][ni][2] + bx, acc[mi][ni][3] + by);
            *reinterpret_cast<float2*>(&C[(size_t)r0 * N_real + col]) = v0;
            *reinterpret_cast<float2*>(&C[(size_t)(r0 + 8) * N_real + col]) = v1;
        }
    }
}

// ---------------- persistent LSTM layer ----------------
#define SM_WS 0
#define SM_SH (16 * 512)                 // 8192 floats
#define SM_GS (SM_SH + 32 * 512)         // 24576
#define SM_CS (SM_GS + 512)              // 25088
#define SM_FLOATS (SM_CS + 128)          // 25216 -> 100864 bytes

__global__ __launch_bounds__(NTHR, 1)
void lstm_layer_persistent(const float* __restrict__ Gx,   // [T*B][2048], rows t*32+b
                           const float* __restrict__ Wh,   // [512][2048]
                           int rA, int rB, unsigned gen_base)
{
    extern __shared__ float smemf[];
    float* ws = smemf + SM_WS;
    float* sh = smemf + SM_SH;
    float* gs = smemf + SM_GS;
    float* cs = smemf + SM_CS;

    int tid = threadIdx.x;
    int e0 = blockIdx.x * 4;
    int b  = tid & 31;
    int cg = tid >> 5;                 // 0..7
    int c0 = cg * 2, c1 = c0 + 1;
    int col0 = ((c0 >> 2) << 9) + e0 + (c0 & 3);
    int col1 = ((c1 >> 2) << 9) + e0 + (c1 & 3);
    int bx7 = b & 7;

    for (int i = tid; i < 16 * 512; i += NTHR) {
        int c = i & 15, k = i >> 4;
        ws[c * 512 + k] = Wh[(size_t)k * 2048 + ((c >> 2) << 9) + e0 + (c & 3)];
    }
    if (tid < 128) cs[tid] = 0.0f;

    unsigned mygen = gen_base;
    unsigned int sh_u32 = (unsigned int)__cvta_generic_to_shared(sh);
    const float4* ws4 = (const float4*)ws;
    const float4* hp  = (const float4*)sh + b * 128;
    const float4* wp0 = ws4 + c0 * 128;
    const float4* wp1 = ws4 + c1 * 128;
    __syncthreads();

    #pragma unroll 1
    for (int t = 0; t < TT; t++) {
        const float* hg_r = g_Hping + ((t & 1) ? (BB * EE) : 0);
        float*       hg_w = g_Hping + ((t & 1) ? 0 : (BB * EE));

        float gx0 = Gx[(size_t)(t * 32 + b) * 2048 + col0];
        float gx1 = Gx[(size_t)(t * 32 + b) * 2048 + col1];

        float acc0 = 0.0f, acc1 = 0.0f;

        if (t > 0) {
            #pragma unroll
            for (int ch = 0; ch < 4; ch++) {
                #pragma unroll
                for (int q = 0; q < 4; q++) {
                    int m  = tid + q * 256;            // 0..1023
                    int bb = m >> 5, kk = m & 31;
                    int src4 = bb * 128 + ch * 32 + kk;
                    int dst4 = bb * 128 + (((ch * 32 + kk)) ^ (bb & 7));
                    cp_async16(sh_u32 + (unsigned int)dst4 * 16u,
                               (const float4*)hg_r + src4);
                }
                cp_commit();
            }

            #define LSTM_CHUNK(CH)                                            \
            {                                                                  \
                _Pragma("unroll")                                              \
                for (int kk = 0; kk < 32; kk++) {                              \
                    float4 hv = hp[((CH) * 32 + kk) ^ bx7];                    \
                    float4 w0 = wp0[(CH) * 32 + kk];                           \
                    float4 w1 = wp1[(CH) * 32 + kk];                           \
                    acc0 += hv.x * w0.x + hv.y * w0.y + hv.z * w0.z + hv.w * w0.w; \
                    acc1 += hv.x * w1.x + hv.y * w1.y + hv.z * w1.z + hv.w * w1.w; \
                }                                                              \
            }

            cp_wait<3>(); __syncthreads(); LSTM_CHUNK(0)
            cp_wait<2>(); __syncthreads(); LSTM_CHUNK(1)
            cp_wait<1>(); __syncthreads(); LSTM_CHUNK(2)
            cp_wait<0>(); __syncthreads(); LSTM_CHUNK(3)
            #undef LSTM_CHUNK
        }

        gs[c0 * 32 + b] = acc0 + gx0;
        gs[c1 * 32 + b] = acc1 + gx1;
        __syncthreads();

        if (tid < 128) {
            int b2 = tid & 31, e2 = tid >> 5;
            float iv = gs[(0  + e2) * 32 + b2];
            float jv = gs[(4  + e2) * 32 + b2];
            float fv = gs[(8  + e2) * 32 + b2];
            float ov = gs[(12 + e2) * 32 + b2];
            float cold = cs[tid];
            float cn = sigm(fv + 1.0f) * cold + sigm(iv) * tanhf(jv);
            float hn = sigm(ov) * tanhf(cn);
            cs[tid] = cn;
            hg_w[b2 * 512 + e0 + e2] = hn;
            size_t row = (size_t)(t * rA + b2 * rB) * EE + e0 + e2;
            __nv_bfloat16 hh = __float2bfloat16(hn);
            g_Ahi[row] = hh;
            g_Alo[row] = __float2bfloat16(hn - __bfloat162float(hh));
            __threadfence();
        }
        grid_barrier(mygen);
    }
}

// ---------------- softmax NLL per row (single pass, online, fast exp) ---------
__global__ void softmax_nll_kernel(const float* __restrict__ logits,
                                   const int* __restrict__ labels)
{
    int row = blockIdx.x;
    const float4* lr = reinterpret_cast<const float4*>(logits + (size_t)row * VV);
    int tid = threadIdx.x;
    __shared__ float redm[256];
    __shared__ float reds[256];

    float m = -1e30f, s = 0.0f;
    for (int i = tid; i < VV / 4; i += 256) {
        float4 v = lr[i];
        float cm = fmaxf(fmaxf(v.x, v.y), fmaxf(v.z, v.w));
        if (cm > m) { s *= __expf(m - cm); m = cm; }
        s += __expf(v.x - m) + __expf(v.y - m) + __expf(v.z - m) + __expf(v.w - m);
    }
    redm[tid] = m; reds[tid] = s;
    __syncthreads();
    for (int st = 128; st > 0; st >>= 1) {
        if (tid < st) {
            float m2 = redm[tid + st], s2 = reds[tid + st];
            float m1 = redm[tid],      s1 = reds[tid];
            float mm = fmaxf(m1, m2);
            redm[tid] = mm;
            reds[tid] = s1 * __expf(m1 - mm) + s2 * __expf(m2 - mm);
        }
        __syncthreads();
    }
    if (tid == 0) {
        float lv = logits[(size_t)row * VV + labels[row]];
        g_nll[row] = redm[0] + logf(reds[0]) - lv;
    }
}

__global__ void perplexity_kernel(float* __restrict__ out, long long out_size) {
    __shared__ float red[256];
    int tid = threadIdx.x;
    float s = 0.f;
    for (int i = tid; i < MROWS; i += 256) s += g_nll[i];
    red[tid] = s; __syncthreads();
    for (int st = 128; st > 0; st >>= 1) {
        if (tid < st) red[tid] += red[tid + st];
        __syncthreads();
    }
    if (tid == 0 && out_size > (long long)MROWS * VV)
        out[out_size - 1] = expf(red[0] / (float)MROWS);
}

// ---------------- host launch ----------------
extern "C" void kernel_launch(void* const* d_in, const int* in_sizes, int n_in,
                              void* d_out, int out_size)
{
    const int*   inputs = (const int*)  d_in[0];
    const int*   labels = (const int*)  d_in[1];
    const float* Emat   = (const float*)d_in[2];
    const float* Wx0    = (const float*)d_in[3];
    const float* Wh0    = (const float*)d_in[4];
    const float* b0     = (const float*)d_in[5];
    const float* Wx1    = (const float*)d_in[6];
    const float* Wh1    = (const float*)d_in[7];
    const float* b1     = (const float*)d_in[8];
    const float* Wd     = (const float*)d_in[9];
    const float* bd     = (const float*)d_in[10];
    float* out = (float*)d_out;

    float *pG;
    __nv_bfloat16 *pAhi, *pAlo;
    cudaGetSymbolAddress((void**)&pG,   g_G);
    cudaGetSymbolAddress((void**)&pAhi, g_Ahi);
    cudaGetSymbolAddress((void**)&pAlo, g_Alo);

    const int lstm_smem = SM_FLOATS * 4;
    cudaFuncSetAttribute(lstm_layer_persistent,
                         cudaFuncAttributeMaxDynamicSharedMemorySize, lstm_smem);
    cudaFuncSetAttribute(gemm_mma,
                         cudaFuncAttributeMaxDynamicSharedMemorySize, GEMM_SMEM);

    dim3 tsblk(32, 8);

    // 0) reset barrier state
    init_kernel<<<1, 32>>>();

    // 1) embedding gather -> split bf16 A operand (rows t*32+b)
    embed_kernel<<<(MROWS * (EE / 4) + 255) / 256, 256>>>(inputs, Emat);

    // 2) Wx0^T split; X0 = xs @ Wx0 + b0 -> g_G
    transpose_split_kernel<<<dim3(GE / 32, 16), tsblk>>>(Wx0, GE, GE);
    gemm_mma<<<dim3(GE / TCN, MROWS / TCM), 128, GEMM_SMEM>>>(pAhi, pAlo, b0, pG, GE, 0);

    // 3) layer-0 persistent scan (writes A = H0, rows t*32+b)
    lstm_layer_persistent<<<NBLK, NTHR, lstm_smem>>>(pG, Wh0,
                                                     /*rA=*/32, /*rB=*/1,
                                                     /*gen_base=*/0u);

    // 4) Wx1^T split; X1 = H0 @ Wx1 + b1 -> g_G
    transpose_split_kernel<<<dim3(GE / 32, 16), tsblk>>>(Wx1, GE, GE);
    gemm_mma<<<dim3(GE / TCN, MROWS / TCM), 128, GEMM_SMEM>>>(pAhi, pAlo, b1, pG, GE, 0);

    // 5) layer-1 persistent scan (writes A = H1, rows b*256+t)
    lstm_layer_persistent<<<NBLK, NTHR, lstm_smem>>>(pG, Wh1,
                                                     /*rA=*/1, /*rB=*/TT,
                                                     /*gen_base=*/(unsigned)TT);

    // 6) Wd^T split (padded to 16128); logits = H1 @ Wd + bd -> d_out
    //    swap_mn=1: wave shares the small A operand in L2 instead of streaming B
    transpose_split_kernel<<<dim3(NPADV / 32, 16), tsblk>>>(Wd, VV, NPADV);
    gemm_mma<<<dim3(MROWS / TCM, NPADV / TCN), 128, GEMM_SMEM>>>(pAhi, pAlo, bd, out, VV, 1);

    // 7) per-row NLL (single pass)
    softmax_nll_kernel<<<MROWS, 256>>>(out, labels);

    // 8) perplexity scalar
    perplexity_kernel<<<1, 256>>>(out, (long long)out_size);
}

// round 12
// speedup vs baseline: 1.2757x; 1.2561x over previous
#include <cuda_runtime.h>
#include <cuda_bf16.h>
#include <cstdint>
#include <math.h>

// Problem dims
#define VV 16000
#define BB 32
#define TT 256
#define EE 512
#define GE 2048          // 4*E
#define MROWS 8192       // B*T
#define NPADV 16128      // 126*128, padded vocab for GEMM tiles

#define NBLK 128
#define NTHR 256

// ---------------- scratch (device globals; no allocation allowed) -------------
__device__ __align__(16) float g_G   [(size_t)MROWS * GE];     // x@Wx+b (reused per layer)
__device__ __align__(16) __nv_bfloat16 g_HpHi[2 * BB * EE];    // h ping-pong hi
__device__ __align__(16) __nv_bfloat16 g_HpLo[2 * BB * EE];    // h ping-pong lo
__device__ __align__(16) __nv_bfloat16 g_Ahi[(size_t)MROWS * EE];   // A operand hi
__device__ __align__(16) __nv_bfloat16 g_Alo[(size_t)MROWS * EE];   // A operand lo
__device__ __align__(16) __nv_bfloat16 g_WThi[(size_t)NPADV * EE];  // W^T hi [Npad][512]
__device__ __align__(16) __nv_bfloat16 g_WTlo[(size_t)NPADV * EE];  // W^T lo
__device__ __align__(16) __nv_bfloat16 g_Wh0Thi[(size_t)GE * EE];   // Wh0^T hi
__device__ __align__(16) __nv_bfloat16 g_Wh0Tlo[(size_t)GE * EE];
__device__ __align__(16) __nv_bfloat16 g_Wh1Thi[(size_t)GE * EE];   // Wh1^T hi
__device__ __align__(16) __nv_bfloat16 g_Wh1Tlo[(size_t)GE * EE];
__device__ float g_nll [MROWS];
__device__ unsigned g_bar_cnt;
__device__ unsigned g_bar_gen;

// ---------------- helpers ----------------
__device__ __forceinline__ float sigm(float x) { return 1.0f / (1.0f + expf(-x)); }

__device__ __forceinline__ unsigned ld_acq(const unsigned* p) {
    unsigned v;
    asm volatile("ld.acquire.gpu.u32 %0, [%1];" : "=r"(v) : "l"(p) : "memory");
    return v;
}

__device__ __forceinline__ void cp_async16(unsigned int dst, const void* src) {
    asm volatile("cp.async.cg.shared.global [%0], [%1], 16;" :: "r"(dst), "l"(src));
}
__device__ __forceinline__ void cp_commit() { asm volatile("cp.async.commit_group;"); }
template<int N> __device__ __forceinline__ void cp_wait() {
    asm volatile("cp.async.wait_group %0;" :: "n"(N));
}

__device__ __forceinline__ void grid_barrier(unsigned& mygen) {
    __syncthreads();
    if (threadIdx.x == 0) {
        unsigned a = atomicAdd(&g_bar_cnt, 1u);
        if (a == NBLK - 1) {
            g_bar_cnt = 0u;
            __threadfence();
            atomicAdd(&g_bar_gen, 1u);
        } else {
            while (ld_acq(&g_bar_gen) == mygen) { }
        }
        mygen++;
    }
    __syncthreads();
}

// ---------------- mma.sync helpers (compute_80 PTX — HMMA on sm_103) ----------
__device__ __forceinline__ void ldsm4(unsigned& r0, unsigned& r1, unsigned& r2,
                                      unsigned& r3, unsigned addr) {
    asm volatile("ldmatrix.sync.aligned.m8n8.x4.shared.b16 {%0,%1,%2,%3}, [%4];"
                 : "=r"(r0), "=r"(r1), "=r"(r2), "=r"(r3) : "r"(addr));
}
__device__ __forceinline__ void mma16816(float* d, const unsigned* a, const unsigned* b) {
    asm volatile(
        "mma.sync.aligned.m16n8k16.row.col.f32.bf16.bf16.f32 "
        "{%0,%1,%2,%3}, {%4,%5,%6,%7}, {%8,%9}, {%0,%1,%2,%3};"
        : "+f"(d[0]), "+f"(d[1]), "+f"(d[2]), "+f"(d[3])
        : "r"(a[0]), "r"(a[1]), "r"(a[2]), "r"(a[3]), "r"(b[0]), "r"(b[1]));
}

// ---------------- init: reset barrier state ----------------
__global__ void init_kernel() {
    if (threadIdx.x == 0) { g_bar_cnt = 0u; g_bar_gen = 0u; }
}

// ---------------- embedding gather -> split bf16 A operand ----------------
__global__ void embed_kernel(const int* __restrict__ inputs, const float* __restrict__ Emat) {
    int idx = blockIdx.x * blockDim.x + threadIdx.x;
    if (idx >= MROWS * (EE / 4)) return;
    int r  = idx >> 7;        // row (t*B+b); E/4 = 128
    int e4 = idx & 127;
    int t = r >> 5;
    int b = r & 31;
    int tok = inputs[b * TT + t];
    float4 v = reinterpret_cast<const float4*>(Emat)[(size_t)tok * 128 + e4];
    size_t base = (size_t)r * EE + e4 * 4;
    __nv_bfloat162 h01 = __floats2bfloat162_rn(v.x, v.y);
    __nv_bfloat162 h23 = __floats2bfloat162_rn(v.z, v.w);
    *reinterpret_cast<__nv_bfloat162*>(&g_Ahi[base])     = h01;
    *reinterpret_cast<__nv_bfloat162*>(&g_Ahi[base + 2]) = h23;
    __nv_bfloat162 l01 = __floats2bfloat162_rn(v.x - __bfloat162float(h01.x),
                                               v.y - __bfloat162float(h01.y));
    __nv_bfloat162 l23 = __floats2bfloat162_rn(v.z - __bfloat162float(h23.x),
                                               v.w - __bfloat162float(h23.y));
    *reinterpret_cast<__nv_bfloat162*>(&g_Alo[base])     = l01;
    *reinterpret_cast<__nv_bfloat162*>(&g_Alo[base + 2]) = l23;
}

// ---------------- weight transpose + bf16 split: W[512][N] -> dst[N][512] -----
__global__ void transpose_split_kernel(const float* __restrict__ W, int N,
                                       __nv_bfloat16* __restrict__ dsthi,
                                       __nv_bfloat16* __restrict__ dstlo) {
    __shared__ float tile[32][33];
    int bx = blockIdx.x * 32;   // n base
    int by = blockIdx.y * 32;   // k base
    int tx = threadIdx.x;       // 0..31
    int ty = threadIdx.y;       // 0..7
    #pragma unroll
    for (int j = 0; j < 4; j++) {
        int k = by + ty + j * 8;
        int n = bx + tx;
        tile[ty + j * 8][tx] = (n < N) ? W[(size_t)k * N + n] : 0.0f;
    }
    __syncthreads();
    #pragma unroll
    for (int j = 0; j < 4; j++) {
        int n = bx + ty + j * 8;
        int k = by + tx;
        float v = tile[tx][ty + j * 8];
        __nv_bfloat16 h = __float2bfloat16(v);
        dsthi[(size_t)n * EE + k] = h;
        dstlo[(size_t)n * EE + k] = __float2bfloat16(v - __bfloat162float(h));
    }
}

// ---------------- bf16 mma GEMM (Round-9 config): C = A*W^T + bias -----------
// K-extension split: K_eff = 3*512; phase 0: Ahi*Bhi, 1: Alo*Bhi, 2: Ahi*Blo.
// Tile 128x128, BK=64, 256 threads (8 warps, 2m x 4n), warp tile 64x32.
#define LDT 72
#define ROWB (LDT * 2)                    // 144
#define TILEA_BYTES (128 * ROWB)          // 18432
#define STAGE_BYTES (2 * TILEA_BYTES)     // 36864
#define NSTAGE 3
#define GEMM_SMEM (NSTAGE * STAGE_BYTES)  // 110592

__global__ __launch_bounds__(256, 2)
void gemm_mma(const __nv_bfloat16* __restrict__ Ahi, const __nv_bfloat16* __restrict__ Alo,
              const float* __restrict__ bias, float* __restrict__ C, int N_real)
{
    extern __shared__ __align__(16) char smem[];
    __shared__ float sbias[128];

    int tid = threadIdx.x;
    int wid = tid >> 5;
    int lane = tid & 31;
    int wm = wid & 1;
    int wn = wid >> 1;
    int n0 = blockIdx.x * 128;
    int m0 = blockIdx.y * 128;

    unsigned sbase = (unsigned)__cvta_generic_to_shared(smem);

    for (int i = tid; i < 128; i += 256) {
        int n = n0 + i;
        sbias[i] = (n < N_real) ? bias[n] : 0.0f;
    }

    int g  = lane >> 3;
    int lr = lane & 7;
    unsigned aoff[4];
    #pragma unroll
    for (int mi = 0; mi < 4; mi++)
        aoff[mi] = (unsigned)((wm * 64 + mi * 16 + (g & 1) * 8 + lr) * ROWB
                              + (g >> 1) * 16);
    unsigned boff[2];
    #pragma unroll
    for (int ni2 = 0; ni2 < 2; ni2++)
        boff[ni2] = (unsigned)(TILEA_BYTES + (wn * 32 + ni2 * 16 + (g >> 1) * 8 + lr) * ROWB
                               + (g & 1) * 16);

    float acc[4][4][4];
    #pragma unroll
    for (int i = 0; i < 4; i++)
        #pragma unroll
        for (int j = 0; j < 4; j++)
            #pragma unroll
            for (int r = 0; r < 4; r++) acc[i][j][r] = 0.0f;

    const int NCH = 24;

    auto load_chunk = [&](int c, int stage) {
        int phase = c >> 3;
        int k0 = (c & 7) * 64;
        const __nv_bfloat16* Asrc = (phase == 1) ? Alo : Ahi;
        const __nv_bfloat16* Bsrc = (phase == 2) ? g_WTlo : g_WThi;
        unsigned dstA = sbase + stage * STAGE_BYTES;
        unsigned dstB = dstA + TILEA_BYTES;
        #pragma unroll
        for (int q = 0; q < 8; q++) {
            int idx = tid + q * 256;
            if (idx < 1024) {
                int row = idx >> 3, gg = idx & 7;
                cp_async16(dstA + row * ROWB + gg * 16,
                           Asrc + (size_t)(m0 + row) * EE + k0 + gg * 8);
            } else {
                int idx2 = idx - 1024;
                int row = idx2 >> 3, gg = idx2 & 7;
                cp_async16(dstB + row * ROWB + gg * 16,
                           Bsrc + (size_t)(n0 + row) * EE + k0 + gg * 8);
            }
        }
        cp_commit();
    };

    load_chunk(0, 0);
    load_chunk(1, 1);

    int stage = 0;
    #pragma unroll 1
    for (int c = 0; c < NCH; c++) {
        if (c + 2 < NCH) cp_wait<1>(); else cp_wait<0>();
        __syncthreads();
        if (c + 2 < NCH)
            load_chunk(c + 2, (c + 2) % NSTAGE);

        unsigned sb = sbase + stage * STAGE_BYTES;
        #pragma unroll
        for (int ks = 0; ks < 4; ks++) {
            unsigned a[4][4], b[4][2];
            #pragma unroll
            for (int mi = 0; mi < 4; mi++)
                ldsm4(a[mi][0], a[mi][1], a[mi][2], a[mi][3],
                      sb + aoff[mi] + ks * 32);
            #pragma unroll
            for (int ni2 = 0; ni2 < 2; ni2++)
                ldsm4(b[2 * ni2][0], b[2 * ni2][1], b[2 * ni2 + 1][0], b[2 * ni2 + 1][1],
                      sb + boff[ni2] + ks * 32);
            #pragma unroll
            for (int mi = 0; mi < 4; mi++)
                #pragma unroll
                for (int ni = 0; ni < 4; ni++)
                    mma16816(acc[mi][ni], a[mi], b[ni]);
        }
        stage = (stage + 1 == NSTAGE) ? 0 : stage + 1;
    }

    int rbase = m0 + wm * 64 + (lane >> 2);
    int cbase = n0 + wn * 32 + 2 * (lane & 3);
    #pragma unroll
    for (int mi = 0; mi < 4; mi++) {
        #pragma unroll
        for (int ni = 0; ni < 4; ni++) {
            int col = cbase + ni * 8;
            if (col >= N_real) continue;
            int cl = (wn * 32 + ni * 8 + 2 * (lane & 3));
            float bx = sbias[cl], by = sbias[cl + 1];
            int r0 = rbase + mi * 16;
            float2 v0 = make_float2(acc[mi][ni][0] + bx, acc[mi][ni][1] + by);
            float2 v1 = make_float2(acc[mi][ni][2] + bx, acc[mi][ni][3] + by);
            *reinterpret_cast<float2*>(&C[(size_t)r0 * N_real + col]) = v0;
            *reinterpret_cast<float2*>(&C[(size_t)(r0 + 8) * N_real + col]) = v1;
        }
    }
}

// ---------------- persistent LSTM layer (tensor-core recurrence) --------------
// 128 blocks x 256 threads (8 warps). Block owns 16 gate-cols (c = g*4+el,
// col = g*512 + e0 + el). h@Wh via mma bf16 3-term split; warp w covers
// K slice [w*64, w*64+64). Wh slice B-fragments persist in registers.
#define HROWB 1040                       // 512 bf16 + 8 pad = conflict-free ldsm
#define LSM_WH_HI 0                      // 16 rows
#define LSM_WH_LO (16 * HROWB)           // 16640
#define LSM_H_HI  (32 * HROWB)           // 33280, 32 rows
#define LSM_H_LO  (LSM_H_HI + 32 * HROWB)        // 66560
#define LSM_RED   (LSM_H_LO + 32 * HROWB)        // 99840, 8*512 floats
#define LSM_GS    (LSM_RED + 8 * 512 * 4)        // 116224, 512 floats
#define LSM_CS    (LSM_GS + 512 * 4)             // 118272, 128 floats
#define LSTM_SMEM (LSM_CS + 512)                 // 118784 bytes

__global__ __launch_bounds__(NTHR, 1)
void lstm_layer_mma(const float* __restrict__ Gx,          // [T*B][2048]
                    const __nv_bfloat16* __restrict__ WhThi,  // [2048][512]
                    const __nv_bfloat16* __restrict__ WhTlo,
                    int rA, int rB, unsigned gen_base)
{
    extern __shared__ __align__(16) char sm[];
    unsigned sbase = (unsigned)__cvta_generic_to_shared(sm);
    float* red = reinterpret_cast<float*>(sm + LSM_RED);
    float* gs  = reinterpret_cast<float*>(sm + LSM_GS);
    float* cs  = reinterpret_cast<float*>(sm + LSM_CS);

    int tid = threadIdx.x;
    int wid = tid >> 5;
    int lane = tid & 31;
    int e0 = blockIdx.x * 4;
    int g  = lane >> 3;
    int lr = lane & 7;

    // one-time: load Wh slice (16 rows: col(c) = (c>>2)*512 + e0 + (c&3))
    #pragma unroll
    for (int q = 0; q < 4; q++) {
        int idx = tid + q * 256;          // 0..1023 over 16 rows x 64 granules
        int c = idx >> 6, kk = idx & 63;
        int grow = (c >> 2) * 512 + e0 + (c & 3);
        cp_async16(sbase + LSM_WH_HI + c * HROWB + kk * 16,
                   WhThi + (size_t)grow * EE + kk * 8);
        cp_async16(sbase + LSM_WH_LO + c * HROWB + kk * 16,
                   WhTlo + (size_t)grow * EE + kk * 8);
    }
    cp_commit();
    if (tid < 128) cs[tid] = 0.0f;
    cp_wait<0>();
    __syncthreads();

    // persistent B fragments for my K slice (4 k-tiles of 16)
    unsigned Bh[4][4], Bl[4][4];
    {
        unsigned rowoff = (unsigned)(((g >> 1) * 8 + lr) * HROWB + (g & 1) * 16);
        #pragma unroll
        for (int kt = 0; kt < 4; kt++) {
            unsigned kb = (unsigned)(wid * 128 + kt * 32);
            ldsm4(Bh[kt][0], Bh[kt][1], Bh[kt][2], Bh[kt][3],
                  sbase + LSM_WH_HI + rowoff + kb);
            ldsm4(Bl[kt][0], Bl[kt][1], Bl[kt][2], Bl[kt][3],
                  sbase + LSM_WH_LO + rowoff + kb);
        }
    }

    // A-fragment address offsets (row-major m16k16, validated scheme)
    unsigned aoff[2];
    #pragma unroll
    for (int mi = 0; mi < 2; mi++)
        aoff[mi] = (unsigned)((mi * 16 + (g & 1) * 8 + lr) * HROWB + (g >> 1) * 16
                              + wid * 128);

    // output indices for reduction (2 per thread)
    int i1 = tid, i2 = tid + 256;
    int c1 = i1 >> 5, b1 = i1 & 31;
    int c2 = i2 >> 5, b2i = i2 & 31;
    int col1 = (c1 >> 2) * 512 + e0 + (c1 & 3);
    int col2 = (c2 >> 2) * 512 + e0 + (c2 & 3);

    unsigned mygen = gen_base;

    #pragma unroll 1
    for (int t = 0; t < TT; t++) {
        const __nv_bfloat16* hi_r = g_HpHi + ((t & 1) ? (BB * EE) : 0);
        const __nv_bfloat16* lo_r = g_HpLo + ((t & 1) ? (BB * EE) : 0);
        __nv_bfloat16* hi_w = g_HpHi + ((t & 1) ? 0 : (BB * EE));
        __nv_bfloat16* lo_w = g_HpLo + ((t & 1) ? 0 : (BB * EE));

        float gx1 = Gx[(size_t)(t * 32 + b1) * 2048 + col1];
        float gx2 = Gx[(size_t)(t * 32 + b2i) * 2048 + col2];

        if (t > 0) {
            // load h (hi+lo) into padded smem: 32 rows x 64 granules each
            #pragma unroll
            for (int q = 0; q < 8; q++) {
                int idx = tid + q * 256;          // 0..2047
                int m = idx >> 6, kk = idx & 63;
                cp_async16(sbase + LSM_H_HI + m * HROWB + kk * 16,
                           hi_r + (size_t)m * EE + kk * 8);
                cp_async16(sbase + LSM_H_LO + m * HROWB + kk * 16,
                           lo_r + (size_t)m * EE + kk * 8);
            }
            cp_commit();
            cp_wait<0>();
            __syncthreads();

            // A fragments
            unsigned Ah[2][4][4], Al[2][4][4];
            #pragma unroll
            for (int mi = 0; mi < 2; mi++)
                #pragma unroll
                for (int kt = 0; kt < 4; kt++) {
                    ldsm4(Ah[mi][kt][0], Ah[mi][kt][1], Ah[mi][kt][2], Ah[mi][kt][3],
                          sbase + LSM_H_HI + aoff[mi] + kt * 32);
                    ldsm4(Al[mi][kt][0], Al[mi][kt][1], Al[mi][kt][2], Al[mi][kt][3],
                          sbase + LSM_H_LO + aoff[mi] + kt * 32);
                }

            float acc[2][2][4];
            #pragma unroll
            for (int mi = 0; mi < 2; mi++)
                #pragma unroll
                for (int ni = 0; ni < 2; ni++)
                    #pragma unroll
                    for (int r = 0; r < 4; r++) acc[mi][ni][r] = 0.0f;

            #pragma unroll
            for (int kt = 0; kt < 4; kt++)
                #pragma unroll
                for (int mi = 0; mi < 2; mi++)
                    #pragma unroll
                    for (int ni = 0; ni < 2; ni++) {
                        mma16816(acc[mi][ni], Ah[mi][kt], &Bh[kt][ni * 2]);
                        mma16816(acc[mi][ni], Al[mi][kt], &Bh[kt][ni * 2]);
                        mma16816(acc[mi][ni], Ah[mi][kt], &Bl[kt][ni * 2]);
                    }

            // store partials: C(m=batch,n=col): red[w*512 + n*32 + m]
            int rrow = lane >> 2;
            int rcol = 2 * (lane & 3);
            #pragma unroll
            for (int mi = 0; mi < 2; mi++)
                #pragma unroll
                for (int ni = 0; ni < 2; ni++) {
                    int m0r = mi * 16 + rrow;
                    int n0c = ni * 8 + rcol;
                    red[wid * 512 + n0c * 32 + m0r]           = acc[mi][ni][0];
                    red[wid * 512 + (n0c + 1) * 32 + m0r]     = acc[mi][ni][1];
                    red[wid * 512 + n0c * 32 + m0r + 8]       = acc[mi][ni][2];
                    red[wid * 512 + (n0c + 1) * 32 + m0r + 8] = acc[mi][ni][3];
                }
        }
        __syncthreads();

        // reduce across 8 warps + add Gx
        float s1 = gx1, s2 = gx2;
        if (t > 0) {
            #pragma unroll
            for (int w = 0; w < 8; w++) {
                s1 += red[w * 512 + i1];
                s2 += red[w * 512 + i2];
            }
        }
        gs[i1] = s1;
        gs[i2] = s2;
        __syncthreads();

        if (tid < 128) {
            int b2 = tid & 31, e2 = tid >> 5;
            float iv = gs[(0  + e2) * 32 + b2];
            float jv = gs[(4  + e2) * 32 + b2];
            float fv = gs[(8  + e2) * 32 + b2];
            float ov = gs[(12 + e2) * 32 + b2];
            float cold = cs[tid];
            float cn = sigm(fv + 1.0f) * cold + sigm(iv) * tanhf(jv);
            float hn = sigm(ov) * tanhf(cn);
            cs[tid] = cn;
            __nv_bfloat16 hh = __float2bfloat16(hn);
            __nv_bfloat16 hl = __float2bfloat16(hn - __bfloat162float(hh));
            int he = e0 + e2;
            hi_w[b2 * EE + he] = hh;
            lo_w[b2 * EE + he] = hl;
            size_t row = (size_t)(t * rA + b2 * rB) * EE + he;
            g_Ahi[row] = hh;
            g_Alo[row] = hl;
            __threadfence();
        }
        grid_barrier(mygen);
    }
}

// ---------------- softmax NLL per row (single pass, online, fast exp) ---------
__global__ void softmax_nll_kernel(const float* __restrict__ logits,
                                   const int* __restrict__ labels)
{
    int row = blockIdx.x;
    const float4* lr = reinterpret_cast<const float4*>(logits + (size_t)row * VV);
    int tid = threadIdx.x;
    __shared__ float redm[256];
    __shared__ float reds[256];

    float m = -1e30f, s = 0.0f;
    for (int i = tid; i < VV / 4; i += 256) {
        float4 v = lr[i];
        float cm = fmaxf(fmaxf(v.x, v.y), fmaxf(v.z, v.w));
        if (cm > m) { s *= __expf(m - cm); m = cm; }
        s += __expf(v.x - m) + __expf(v.y - m) + __expf(v.z - m) + __expf(v.w - m);
    }
    redm[tid] = m; reds[tid] = s;
    __syncthreads();
    for (int st = 128; st > 0; st >>= 1) {
        if (tid < st) {
            float m2 = redm[tid + st], s2 = reds[tid + st];
            float m1 = redm[tid],      s1 = reds[tid];
            float mm = fmaxf(m1, m2);
            redm[tid] = mm;
            reds[tid] = s1 * __expf(m1 - mm) + s2 * __expf(m2 - mm);
        }
        __syncthreads();
    }
    if (tid == 0) {
        float lv = logits[(size_t)row * VV + labels[row]];
        g_nll[row] = redm[0] + logf(reds[0]) - lv;
    }
}

__global__ void perplexity_kernel(float* __restrict__ out, long long out_size) {
    __shared__ float red[256];
    int tid = threadIdx.x;
    float s = 0.f;
    for (int i = tid; i < MROWS; i += 256) s += g_nll[i];
    red[tid] = s; __syncthreads();
    for (int st = 128; st > 0; st >>= 1) {
        if (tid < st) red[tid] += red[tid + st];
        __syncthreads();
    }
    if (tid == 0 && out_size > (long long)MROWS * VV)
        out[out_size - 1] = expf(red[0] / (float)MROWS);
}

// ---------------- host launch ----------------
extern "C" void kernel_launch(void* const* d_in, const int* in_sizes, int n_in,
                              void* d_out, int out_size)
{
    const int*   inputs = (const int*)  d_in[0];
    const int*   labels = (const int*)  d_in[1];
    const float* Emat   = (const float*)d_in[2];
    const float* Wx0    = (const float*)d_in[3];
    const float* Wh0    = (const float*)d_in[4];
    const float* b0     = (const float*)d_in[5];
    const float* Wx1    = (const float*)d_in[6];
    const float* Wh1    = (const float*)d_in[7];
    const float* b1     = (const float*)d_in[8];
    const float* Wd     = (const float*)d_in[9];
    const float* bd     = (const float*)d_in[10];
    float* out = (float*)d_out;

    float *pG;
    __nv_bfloat16 *pAhi, *pAlo, *pWThi, *pWTlo;
    __nv_bfloat16 *pWh0Thi, *pWh0Tlo, *pWh1Thi, *pWh1Tlo;
    cudaGetSymbolAddress((void**)&pG,   g_G);
    cudaGetSymbolAddress((void**)&pAhi, g_Ahi);
    cudaGetSymbolAddress((void**)&pAlo, g_Alo);
    cudaGetSymbolAddress((void**)&pWThi, g_WThi);
    cudaGetSymbolAddress((void**)&pWTlo, g_WTlo);
    cudaGetSymbolAddress((void**)&pWh0Thi, g_Wh0Thi);
    cudaGetSymbolAddress((void**)&pWh0Tlo, g_Wh0Tlo);
    cudaGetSymbolAddress((void**)&pWh1Thi, g_Wh1Thi);
    cudaGetSymbolAddress((void**)&pWh1Tlo, g_Wh1Tlo);

    cudaFuncSetAttribute(lstm_layer_mma,
                         cudaFuncAttributeMaxDynamicSharedMemorySize, LSTM_SMEM);
    cudaFuncSetAttribute(gemm_mma,
                         cudaFuncAttributeMaxDynamicSharedMemorySize, GEMM_SMEM);

    dim3 tsblk(32, 8);

    // 0) reset barrier state
    init_kernel<<<1, 32>>>();

    // 1) embedding gather -> split bf16 A operand (rows t*32+b)
    embed_kernel<<<(MROWS * (EE / 4) + 255) / 256, 256>>>(inputs, Emat);

    // 1b) recurrent weight transposes (independent of data flow)
    transpose_split_kernel<<<dim3(GE / 32, 16), tsblk>>>(Wh0, GE, pWh0Thi, pWh0Tlo);
    transpose_split_kernel<<<dim3(GE / 32, 16), tsblk>>>(Wh1, GE, pWh1Thi, pWh1Tlo);

    // 2) Wx0^T split; X0 = xs @ Wx0 + b0 -> g_G
    transpose_split_kernel<<<dim3(GE / 32, 16), tsblk>>>(Wx0, GE, pWThi, pWTlo);
    gemm_mma<<<dim3(GE / 128, MROWS / 128), 256, GEMM_SMEM>>>(pAhi, pAlo, b0, pG, GE);

    // 3) layer-0 persistent scan (writes A = H0, rows t*32+b)
    lstm_layer_mma<<<NBLK, NTHR, LSTM_SMEM>>>(pG, pWh0Thi, pWh0Tlo,
                                              /*rA=*/32, /*rB=*/1, /*gen_base=*/0u);

    // 4) Wx1^T split; X1 = H0 @ Wx1 + b1 -> g_G
    transpose_split_kernel<<<dim3(GE / 32, 16), tsblk>>>(Wx1, GE, pWThi, pWTlo);
    gemm_mma<<<dim3(GE / 128, MROWS / 128), 256, GEMM_SMEM>>>(pAhi, pAlo, b1, pG, GE);

    // 5) layer-1 persistent scan (writes A = H1, rows b*256+t)
    lstm_layer_mma<<<NBLK, NTHR, LSTM_SMEM>>>(pG, pWh1Thi, pWh1Tlo,
                                              /*rA=*/1, /*rB=*/TT,
                                              /*gen_base=*/(unsigned)TT);

    // 6) Wd^T split (padded to 16128); logits = H1 @ Wd + bd -> d_out
    transpose_split_kernel<<<dim3(NPADV / 32, 16), tsblk>>>(Wd, VV, pWThi, pWTlo);
    gemm_mma<<<dim3(NPADV / 128, MROWS / 128), 256, GEMM_SMEM>>>(pAhi, pAlo, bd, out, VV);

    // 7) per-row NLL (single pass)
    softmax_nll_kernel<<<MROWS, 256>>>(out, labels);

    // 8) perplexity scalar
    perplexity_kernel<<<1, 256>>>(out, (long long)out_size);
}